// round 7
// baseline (speedup 1.0000x reference)
#include <cuda_runtime.h>

#define B_   4
#define N_   4096
#define K_   512
#define NT   32                 // children per CTA
#define NPAIR (NT/2)            // 16
#define GRID_X (N_/NT)          // 128
#define GRID_TOTAL (GRID_X*B_)  // 512
#define NTHR 256                // thread owns parents 2*tid, 2*tid+1
#define DEPTH 4                 // A prefetch depth (iters); 2 float2 loads/iter
#define EPSF 1e-6f

typedef unsigned long long ull;

__device__ double   g_blkP[GRID_TOTAL];
__device__ double   g_blkC[GRID_TOTAL];
__device__ float    g_blkM[GRID_TOTAL];
__device__ unsigned g_cnt;   // zero-init; atomicInc wrap resets each launch

__device__ __forceinline__ ull pack2(float lo, float hi) {
    ull r; asm("mov.b64 %0, {%1, %2};" : "=l"(r) : "f"(lo), "f"(hi)); return r;
}
__device__ __forceinline__ float2 unpack2(ull v) {
    float2 r; asm("mov.b64 {%0, %1}, %2;" : "=f"(r.x), "=f"(r.y) : "l"(v)); return r;
}
__device__ __forceinline__ ull fma2(ull a, ull b, ull c) {
    ull d; asm("fma.rn.f32x2 %0, %1, %2, %3;" : "=l"(d) : "l"(a), "l"(b), "l"(c)); return d;
}
__device__ __forceinline__ ull mul2(ull a, ull b) {
    ull d; asm("mul.rn.f32x2 %0, %1, %2;" : "=l"(d) : "l"(a), "l"(b)); return d;
}
__device__ __forceinline__ ull add2(ull a, ull b) {
    ull d; asm("add.rn.f32x2 %0, %1, %2;" : "=l"(d) : "l"(a), "l"(b)); return d;
}
__device__ __forceinline__ void lds2(unsigned addr, ull& x, ull& y) {
    asm("ld.shared.v2.b64 {%0, %1}, [%2];" : "=l"(x), "=l"(y) : "r"(addr));
}

// symmetric 3x3 inverse of (S + eps*I)
__device__ __forceinline__ void inv3sym(const float* __restrict__ S,
                                        float& i00, float& i01, float& i02,
                                        float& i11, float& i12, float& i22) {
    float s00 = S[0] + EPSF, s01 = S[1], s02 = S[2];
    float s11 = S[4] + EPSF, s12 = S[5];
    float s22 = S[8] + EPSF;
    float c00 = s11 * s22 - s12 * s12;
    float c01 = s02 * s12 - s01 * s22;
    float c02 = s01 * s12 - s02 * s11;
    float c11 = s00 * s22 - s02 * s02;
    float c12 = s01 * s02 - s00 * s12;
    float c22 = s00 * s11 - s01 * s01;
    float det = s00 * c00 + s01 * c01 + s02 * c02;
    float id  = 1.0f / det;
    i00 = c00 * id; i01 = c01 * id; i02 = c02 * id;
    i11 = c11 * id; i12 = c12 * id; i22 = c22 * id;
}

struct PFeat { ull Pn0, Pn1, Pn2, PI00, PI11, PI22, PI01, PI02, PI12; };

__device__ __forceinline__ PFeat load_parent(const float* SP, const float* muP,
                                             int b, int k) {
    float i00, i01, i02, i11, i12, i22;
    inv3sym(SP + (size_t)(b * K_ + k) * 9, i00, i01, i02, i11, i12, i22);
    const float* mp = muP + (size_t)(b * K_ + k) * 3;
    float p0 = mp[0], p1 = mp[1], p2 = mp[2];
    PFeat f;
    f.Pn0  = pack2(-p0, -p0); f.Pn1 = pack2(-p1, -p1); f.Pn2 = pack2(-p2, -p2);
    f.PI00 = pack2(i00, i00); f.PI11 = pack2(i11, i11); f.PI22 = pack2(i22, i22);
    f.PI01 = pack2(2.f * i01, 2.f * i01);
    f.PI02 = pack2(2.f * i02, 2.f * i02);
    f.PI12 = pack2(2.f * i12, 2.f * i12);
    return f;
}

// one (n-pair x one-parent) update; split 3-chains for ILP
__device__ __forceinline__ void body_k(const PFeat& P,
                                       ull Fc0, ull Fc1, ull Fc2,
                                       ull FI00, ull FI11, ull FI22,
                                       ull FI01, ull FI02, ull FI12,
                                       ull am, ull& accP, ull& accC) {
    ull d0 = add2(Fc0, P.Pn0);
    ull d1 = add2(Fc1, P.Pn1);
    ull d2 = add2(Fc2, P.Pn2);
    ull dd00 = mul2(d0, d0);
    ull dd11 = mul2(d1, d1);
    ull dd22 = mul2(d2, d2);
    ull dd01 = mul2(d0, d1);
    ull dd02 = mul2(d0, d2);
    ull dd12 = mul2(d1, d2);

    ull pa = mul2(dd00, P.PI00);
    pa = fma2(dd01, P.PI01, pa);
    pa = fma2(dd02, P.PI02, pa);
    ull pb = mul2(dd11, P.PI11);
    pb = fma2(dd22, P.PI22, pb);
    pb = fma2(dd12, P.PI12, pb);

    ull ca = mul2(dd00, FI00);
    ca = fma2(dd01, FI01, ca);
    ca = fma2(dd02, FI02, ca);
    ull cb = mul2(dd11, FI11);
    cb = fma2(dd22, FI22, cb);
    cb = fma2(dd12, FI12, cb);

    accP = fma2(am, pa, accP);
    accP = fma2(am, pb, accP);
    accC = fma2(am, ca, accC);
    accC = fma2(am, cb, accC);
}

__global__ void __launch_bounds__(NTHR, 2)
loss_kernel(const float* __restrict__ muC, const float* __restrict__ SC,
            const float* __restrict__ muP, const float* __restrict__ SP,
            const float* __restrict__ A,   const float* __restrict__ mask,
            float* __restrict__ out)
{
    // per n-pair child features, interleaved {even,odd}:
    // c0,c1,c2, I00,I11,I22, 2*I01,2*I02,2*I12, m  -> 10 x 2 floats = 80B
    __shared__ float sh[NPAIR * 20];
    __shared__ float redP[8], redC[8];
    __shared__ float sMask;
    __shared__ int   sLast;

    const int b   = blockIdx.y;
    const int n0  = blockIdx.x * NT;
    const int tid = threadIdx.x;

    PFeat P1 = load_parent(SP, muP, b, 2 * tid);
    PFeat P2 = load_parent(SP, muP, b, 2 * tid + 1);

    // ---- child features -> shared (threads 0..NT-1, one child each) ----
    if (tid < NT) {
        int n = n0 + tid;
        float j00, j01, j02, j11, j12, j22;
        inv3sym(SC + (size_t)(b * N_ + n) * 9, j00, j01, j02, j11, j12, j22);
        const float* mc = muC + (size_t)(b * N_ + n) * 3;
        float* d = &sh[(tid >> 1) * 20 + (tid & 1)];
        d[0]  = mc[0];        d[2]  = mc[1];        d[4]  = mc[2];
        d[6]  = j00;          d[8]  = j11;          d[10] = j22;
        d[12] = 2.f * j01;    d[14] = 2.f * j02;    d[16] = 2.f * j12;
        d[18] = mask[b * N_ + n];
    }
    __syncthreads();

    // block mask partial: warp 0, lanes 0..NPAIR-1
    if (tid < 32) {
        float m = (tid < NPAIR) ? (sh[tid * 20 + 18] + sh[tid * 20 + 19]) : 0.f;
#pragma unroll
        for (int off = 16; off; off >>= 1)
            m += __shfl_down_sync(0xffffffffu, m, off);
        if (tid == 0) sMask = m;
    }

    unsigned sbase = (unsigned)__cvta_generic_to_shared(sh);
    // thread owns k0=2tid, k1=2tid+1 -> one float2 per n-row
    const float2* Ap = (const float2*)(A + ((size_t)b * N_ + n0) * K_) + tid;

    // depth-4 prefetch, 2 float2 per iter (rows n, n+1)
    float2 abuf[2 * DEPTH];
#pragma unroll
    for (int i = 0; i < DEPTH; i++) {
        abuf[2 * i]     = __ldcs(Ap);
        abuf[2 * i + 1] = __ldcs(Ap + K_ / 2);
        Ap += K_;
    }

    ull accP = 0ull, accC = 0ull;

#pragma unroll 4
    for (int p = 0; p < NPAIR; ++p) {
        int s = (p & (DEPTH - 1)) * 2;
        float2 av0 = abuf[s];       // row n:   (k0, k1)
        float2 av1 = abuf[s + 1];   // row n+1: (k0, k1)
        if (p < NPAIR - DEPTH) {
            abuf[s]     = __ldcs(Ap);
            abuf[s + 1] = __ldcs(Ap + K_ / 2);
            Ap += K_;
        }
        unsigned ad = sbase + p * 80;
        ull Fc0, Fc1, Fc2, FI00, FI11, FI22, FI01, FI02, FI12, Fm;
        lds2(ad,      Fc0,  Fc1 );
        lds2(ad + 16, Fc2,  FI00);
        lds2(ad + 32, FI11, FI22);
        lds2(ad + 48, FI01, FI02);
        lds2(ad + 64, FI12, Fm  );

        ull am0 = mul2(pack2(av0.x, av1.x), Fm);   // parent k0: A*mask for {n, n+1}
        ull am1 = mul2(pack2(av0.y, av1.y), Fm);   // parent k1
        body_k(P1, Fc0, Fc1, Fc2, FI00, FI11, FI22, FI01, FI02, FI12, am0, accP, accC);
        body_k(P2, Fc0, Fc1, Fc2, FI00, FI11, FI22, FI01, FI02, FI12, am1, accP, accC);
    }

    // ---- in-block reduction ----
    float2 vP = unpack2(accP), vC = unpack2(accC);
    float sp = vP.x + vP.y;
    float sc = vC.x + vC.y;
#pragma unroll
    for (int off = 16; off; off >>= 1) {
        sp += __shfl_down_sync(0xffffffffu, sp, off);
        sc += __shfl_down_sync(0xffffffffu, sc, off);
    }
    int wid = tid >> 5, lane = tid & 31;
    if (lane == 0) { redP[wid] = sp; redC[wid] = sc; }
    __syncthreads();

    const int bid = blockIdx.y * gridDim.x + blockIdx.x;
    if (tid == 0) {
        float tp = 0.f, tc = 0.f;
#pragma unroll
        for (int i = 0; i < 8; i++) { tp += redP[i]; tc += redC[i]; }
        g_blkP[bid] = (double)tp;
        g_blkC[bid] = (double)tc;
        g_blkM[bid] = sMask;
        __threadfence();
        unsigned t = atomicInc(&g_cnt, GRID_TOTAL - 1);
        sLast = (t == GRID_TOTAL - 1);
    }
    __syncthreads();

    // ---- last block: final reduction + output ----
    if (sLast) {
        __threadfence();
        __shared__ double fP[8], fC[8];
        __shared__ float  fM[8];
        double p = g_blkP[tid] + g_blkP[tid + NTHR];   // 512 slots
        double c = g_blkC[tid] + g_blkC[tid + NTHR];
        float  m = g_blkM[tid] + g_blkM[tid + NTHR];
#pragma unroll
        for (int off = 16; off; off >>= 1) {
            p += __shfl_down_sync(0xffffffffu, p, off);
            c += __shfl_down_sync(0xffffffffu, c, off);
            m += __shfl_down_sync(0xffffffffu, m, off);
        }
        if (lane == 0) { fP[wid] = p; fC[wid] = c; fM[wid] = m; }
        __syncthreads();
        if (tid == 0) {
            double tp = 0.0, tc = 0.0;
            float  tm = 0.f;
#pragma unroll
            for (int i = 0; i < 8; i++) { tp += fP[i]; tc += fC[i]; tm += fM[i]; }
            double denom = (tm > 1.f) ? (double)tm : 1.0;
            out[0] = (float)((tp + tc) / denom);  // final_loss
            out[1] = (float)(tp / denom);          // dist_p_m
            out[2] = (float)(tc / denom);          // dist_c_m
        }
    }
}

extern "C" void kernel_launch(void* const* d_in, const int* in_sizes, int n_in,
                              void* d_out, int out_size) {
    const float* muC  = (const float*)d_in[0];
    const float* SC   = (const float*)d_in[1];
    const float* muP  = (const float*)d_in[2];
    const float* SP   = (const float*)d_in[3];
    const float* A    = (const float*)d_in[4];
    const float* mask = (const float*)d_in[5];

    dim3 grid(GRID_X, B_);
    loss_kernel<<<grid, NTHR>>>(muC, SC, muP, SP, A, mask, (float*)d_out);
}

// round 8
// speedup vs baseline: 1.1115x; 1.1115x over previous
#include <cuda_runtime.h>

#define B_   4
#define N_   4096
#define K_   512
#define NT   32                 // children per CTA
#define GRID_X (N_/NT)          // 128
#define GRID_TOTAL (GRID_X*B_)  // 512
#define NTHR 256                // thread owns parents 2*tid, 2*tid+1 (packed in f32x2 lanes)
#define DEPTH 4                 // A prefetch depth (one float2 per iter)
#define EPSF 1e-6f

typedef unsigned long long ull;

__device__ double   g_blkP[GRID_TOTAL];
__device__ double   g_blkC[GRID_TOTAL];
__device__ float    g_blkM[GRID_TOTAL];
__device__ unsigned g_cnt;   // zero-init; atomicInc wrap resets each launch

__device__ __forceinline__ ull pack2(float lo, float hi) {
    ull r; asm("mov.b64 %0, {%1, %2};" : "=l"(r) : "f"(lo), "f"(hi)); return r;
}
__device__ __forceinline__ float2 unpack2(ull v) {
    float2 r; asm("mov.b64 {%0, %1}, %2;" : "=f"(r.x), "=f"(r.y) : "l"(v)); return r;
}
__device__ __forceinline__ ull fma2(ull a, ull b, ull c) {
    ull d; asm("fma.rn.f32x2 %0, %1, %2, %3;" : "=l"(d) : "l"(a), "l"(b), "l"(c)); return d;
}
__device__ __forceinline__ ull mul2(ull a, ull b) {
    ull d; asm("mul.rn.f32x2 %0, %1, %2;" : "=l"(d) : "l"(a), "l"(b)); return d;
}
__device__ __forceinline__ ull add2(ull a, ull b) {
    ull d; asm("add.rn.f32x2 %0, %1, %2;" : "=l"(d) : "l"(a), "l"(b)); return d;
}
__device__ __forceinline__ void lds2(unsigned addr, ull& x, ull& y) {
    asm("ld.shared.v2.b64 {%0, %1}, [%2];" : "=l"(x), "=l"(y) : "r"(addr));
}

// symmetric 3x3 inverse of (S + eps*I)
__device__ __forceinline__ void inv3sym(const float* __restrict__ S,
                                        float& i00, float& i01, float& i02,
                                        float& i11, float& i12, float& i22) {
    float s00 = S[0] + EPSF, s01 = S[1], s02 = S[2];
    float s11 = S[4] + EPSF, s12 = S[5];
    float s22 = S[8] + EPSF;
    float c00 = s11 * s22 - s12 * s12;
    float c01 = s02 * s12 - s01 * s22;
    float c02 = s01 * s12 - s02 * s11;
    float c11 = s00 * s22 - s02 * s02;
    float c12 = s01 * s02 - s00 * s12;
    float c22 = s00 * s11 - s01 * s01;
    float det = s00 * c00 + s01 * c01 + s02 * c02;
    float id  = 1.0f / det;
    i00 = c00 * id; i01 = c01 * id; i02 = c02 * id;
    i11 = c11 * id; i12 = c12 * id; i22 = c22 * id;
}

__global__ void __launch_bounds__(NTHR, 3)
loss_kernel(const float* __restrict__ muC, const float* __restrict__ SC,
            const float* __restrict__ muP, const float* __restrict__ SP,
            const float* __restrict__ A,   const float* __restrict__ mask,
            float* __restrict__ out)
{
    // per child n: 10 features, each DUPLICATED {v,v} -> 80B:
    // c0,c1,c2, J00,J11,J22, 2J01,2J02,2J12, m
    __shared__ float sh[NT * 20];
    __shared__ float redP[8], redC[8];
    __shared__ float sMask;
    __shared__ int   sLast;

    const int b   = blockIdx.y;
    const int n0  = blockIdx.x * NT;
    const int tid = threadIdx.x;
    const int k0  = 2 * tid;           // parents k0, k0+1 live in the two f32x2 lanes

    // ---- parent-pair features, packed {k0, k1} (9 ull = 18 regs) ----
    float a00, a01, a02, a11, a12, a22;   // parent k0 inverse
    float b00, b01, b02, b11, b12, b22;   // parent k1 inverse
    inv3sym(SP + (size_t)(b * K_ + k0) * 9,     a00, a01, a02, a11, a12, a22);
    inv3sym(SP + (size_t)(b * K_ + k0 + 1) * 9, b00, b01, b02, b11, b12, b22);
    const float* mpA = muP + (size_t)(b * K_ + k0) * 3;
    const float* mpB = muP + (size_t)(b * K_ + k0 + 1) * 3;
    ull Pn0  = pack2(-mpA[0], -mpB[0]);
    ull Pn1  = pack2(-mpA[1], -mpB[1]);
    ull Pn2  = pack2(-mpA[2], -mpB[2]);
    ull PI00 = pack2(a00, b00);
    ull PI11 = pack2(a11, b11);
    ull PI22 = pack2(a22, b22);
    ull PI01 = pack2(2.f * a01, 2.f * b01);
    ull PI02 = pack2(2.f * a02, 2.f * b02);
    ull PI12 = pack2(2.f * a12, 2.f * b12);

    // ---- child features -> shared, duplicated {v,v} ----
    if (tid < NT) {
        int n = n0 + tid;
        float j00, j01, j02, j11, j12, j22;
        inv3sym(SC + (size_t)(b * N_ + n) * 9, j00, j01, j02, j11, j12, j22);
        const float* mc = muC + (size_t)(b * N_ + n) * 3;
        float m = mask[b * N_ + n];
        float* d = &sh[tid * 20];
        d[0]  = mc[0];      d[1]  = mc[0];
        d[2]  = mc[1];      d[3]  = mc[1];
        d[4]  = mc[2];      d[5]  = mc[2];
        d[6]  = j00;        d[7]  = j00;
        d[8]  = j11;        d[9]  = j11;
        d[10] = j22;        d[11] = j22;
        d[12] = 2.f * j01;  d[13] = 2.f * j01;
        d[14] = 2.f * j02;  d[15] = 2.f * j02;
        d[16] = 2.f * j12;  d[17] = 2.f * j12;
        d[18] = m;          d[19] = m;
    }
    __syncthreads();

    // block mask partial: warp 0, lane i owns child i (NT=32)
    if (tid < 32) {
        float m = sh[tid * 20 + 18];
#pragma unroll
        for (int off = 16; off; off >>= 1)
            m += __shfl_down_sync(0xffffffffu, m, off);
        if (tid == 0) sMask = m;
    }

    unsigned sbase = (unsigned)__cvta_generic_to_shared(sh);
    // A row n, parents (k0, k0+1): one float2 per iteration
    const float2* Ap = (const float2*)(A + ((size_t)b * N_ + n0) * K_) + tid;

    float2 abuf[DEPTH];
#pragma unroll
    for (int i = 0; i < DEPTH; i++) {
        abuf[i] = __ldcs(Ap);
        Ap += K_ / 2;
    }

    ull accP = 0ull, accC = 0ull;

#pragma unroll 8
    for (int n = 0; n < NT; ++n) {
        float2 av = abuf[n & (DEPTH - 1)];
        if (n < NT - DEPTH) {
            abuf[n & (DEPTH - 1)] = __ldcs(Ap);
            Ap += K_ / 2;
        }
        unsigned ad = sbase + n * 80;
        ull Fc0, Fc1, Fc2, FJ00, FJ11, FJ22, FJ01, FJ02, FJ12, Fm;
        lds2(ad,      Fc0,  Fc1 );
        lds2(ad + 16, Fc2,  FJ00);
        lds2(ad + 32, FJ11, FJ22);
        lds2(ad + 48, FJ01, FJ02);
        lds2(ad + 64, FJ12, Fm  );

        ull d0 = add2(Fc0, Pn0);      // {c - p(k0), c - p(k1)}
        ull d1 = add2(Fc1, Pn1);
        ull d2 = add2(Fc2, Pn2);

        // term-by-term: dd lives 2 instructions
        ull dd, mp, mc;
        dd = mul2(d0, d0);
        mp = mul2(dd, PI00);  mc = mul2(dd, FJ00);
        dd = mul2(d1, d1);
        mp = fma2(dd, PI11, mp);  mc = fma2(dd, FJ11, mc);
        dd = mul2(d2, d2);
        mp = fma2(dd, PI22, mp);  mc = fma2(dd, FJ22, mc);
        dd = mul2(d0, d1);
        mp = fma2(dd, PI01, mp);  mc = fma2(dd, FJ01, mc);
        dd = mul2(d0, d2);
        mp = fma2(dd, PI02, mp);  mc = fma2(dd, FJ02, mc);
        dd = mul2(d1, d2);
        mp = fma2(dd, PI12, mp);  mc = fma2(dd, FJ12, mc);

        ull am = mul2(pack2(av.x, av.y), Fm);   // {A(n,k0), A(n,k1)} * mask(n)
        accP = fma2(am, mp, accP);
        accC = fma2(am, mc, accC);
    }

    // ---- in-block reduction ----
    float2 vP = unpack2(accP), vC = unpack2(accC);
    float sp = vP.x + vP.y;
    float sc = vC.x + vC.y;
#pragma unroll
    for (int off = 16; off; off >>= 1) {
        sp += __shfl_down_sync(0xffffffffu, sp, off);
        sc += __shfl_down_sync(0xffffffffu, sc, off);
    }
    int wid = tid >> 5, lane = tid & 31;
    if (lane == 0) { redP[wid] = sp; redC[wid] = sc; }
    __syncthreads();

    const int bid = blockIdx.y * gridDim.x + blockIdx.x;
    if (tid == 0) {
        float tp = 0.f, tc = 0.f;
#pragma unroll
        for (int i = 0; i < 8; i++) { tp += redP[i]; tc += redC[i]; }
        g_blkP[bid] = (double)tp;
        g_blkC[bid] = (double)tc;
        g_blkM[bid] = sMask;
        __threadfence();
        unsigned t = atomicInc(&g_cnt, GRID_TOTAL - 1);
        sLast = (t == GRID_TOTAL - 1);
    }
    __syncthreads();

    // ---- last block: final reduction + output ----
    if (sLast) {
        __threadfence();
        __shared__ double fP[8], fC[8];
        __shared__ float  fM[8];
        double p = g_blkP[tid] + g_blkP[tid + NTHR];   // 512 slots
        double c = g_blkC[tid] + g_blkC[tid + NTHR];
        float  m = g_blkM[tid] + g_blkM[tid + NTHR];
#pragma unroll
        for (int off = 16; off; off >>= 1) {
            p += __shfl_down_sync(0xffffffffu, p, off);
            c += __shfl_down_sync(0xffffffffu, c, off);
            m += __shfl_down_sync(0xffffffffu, m, off);
        }
        if (lane == 0) { fP[wid] = p; fC[wid] = c; fM[wid] = m; }
        __syncthreads();
        if (tid == 0) {
            double tp = 0.0, tc = 0.0;
            float  tm = 0.f;
#pragma unroll
            for (int i = 0; i < 8; i++) { tp += fP[i]; tc += fC[i]; tm += fM[i]; }
            double denom = (tm > 1.f) ? (double)tm : 1.0;
            out[0] = (float)((tp + tc) / denom);  // final_loss
            out[1] = (float)(tp / denom);          // dist_p_m
            out[2] = (float)(tc / denom);          // dist_c_m
        }
    }
}

extern "C" void kernel_launch(void* const* d_in, const int* in_sizes, int n_in,
                              void* d_out, int out_size) {
    const float* muC  = (const float*)d_in[0];
    const float* SC   = (const float*)d_in[1];
    const float* muP  = (const float*)d_in[2];
    const float* SP   = (const float*)d_in[3];
    const float* A    = (const float*)d_in[4];
    const float* mask = (const float*)d_in[5];

    dim3 grid(GRID_X, B_);
    loss_kernel<<<grid, NTHR>>>(muC, SC, muP, SP, A, mask, (float*)d_out);
}